// round 5
// baseline (speedup 1.0000x reference)
#include <cuda_runtime.h>
#include <cstdint>

#define N_NODES 100000
#define N_EDGES 1600000
#define IN_F    128
#define OUT_F   32

// Scratch: __device__ globals (no allocation allowed anywhere in this file).
// d_out is touched ONLY with plain coalesced stores in k_finalize.
__device__ int   g_deg[N_NODES];
__device__ float g_dis[N_NODES];
__device__ float g_h  [N_NODES * OUT_F];   // h = x @ W^T
__device__ float g_acc[N_NODES * OUT_F];   // aggregation accumulator

// ---------------------------------------------------------------------------
// K1: deg = 1 (self loop)
__global__ void k_deg_init() {
    int i = blockIdx.x * blockDim.x + threadIdx.x;
    if (i < N_NODES) g_deg[i] = 1;
}

// K2: deg[dst] += 1 per edge.  edge_index arrives as int32 (harness downcasts
// int64 inputs — see stub contract: "int32 -> const int*").
__global__ void k_deg_count(const int* __restrict__ ei) {
    int e = blockIdx.x * blockDim.x + threadIdx.x;
    if (e < N_EDGES) {
        int dst = ei[N_EDGES + e];
        if ((unsigned)dst < N_NODES)           // diagnostic guard (no-op if dtype theory holds)
            atomicAdd(&g_deg[dst], 1);
    }
}

// K3: dis = rsqrt(deg)   (deg >= 1 always)
__global__ void k_dis() {
    int i = blockIdx.x * blockDim.x + threadIdx.x;
    if (i < N_NODES) g_dis[i] = rsqrtf((float)g_deg[i]);
}

// ---------------------------------------------------------------------------
// K4: h = x @ W^T ; g_acc = h * dis^2  (self-loop term, plain store)
// 1024 threads = 32 warps; warp -> node; lane = out feature.
// W transposed in shared (conflict-free); x read as warp-broadcast float4 LDG.
#define NODES_PER_BLK 32
__global__ __launch_bounds__(1024) void k_linear(const float* __restrict__ x,
                                                 const float* __restrict__ W) {
    __shared__ float sWt[IN_F][OUT_F + 1];   // [k][f], padded

    int tid = threadIdx.x;
    #pragma unroll
    for (int i = 0; i < 4; i++) {            // 4096 W elems / 1024 threads
        int idx = tid + i * 1024;
        int f = idx / IN_F;
        int k = idx % IN_F;
        sWt[k][f] = W[idx];
    }
    __syncthreads();

    int ln   = tid >> 5;
    int f    = tid & 31;
    int node = blockIdx.x * NODES_PER_BLK + ln;
    if (node >= N_NODES) return;

    const float4* xr = (const float4*)(x + (size_t)node * IN_F);
    float acc = 0.0f;
    #pragma unroll
    for (int k4 = 0; k4 < IN_F / 4; k4++) {
        float4 xv = xr[k4];                  // warp-broadcast load
        int k = k4 * 4;
        acc = fmaf(xv.x, sWt[k + 0][f], acc);
        acc = fmaf(xv.y, sWt[k + 1][f], acc);
        acc = fmaf(xv.z, sWt[k + 2][f], acc);
        acc = fmaf(xv.w, sWt[k + 3][f], acc);
    }

    g_h[node * OUT_F + f] = acc;
    float d = g_dis[node];
    g_acc[node * OUT_F + f] = acc * d * d;
}

// ---------------------------------------------------------------------------
// K5: edge scatter. One warp per edge; lane = feature. Atomics on g_acc only.
__global__ __launch_bounds__(256) void k_scatter(const int* __restrict__ ei) {
    int gtid = blockIdx.x * blockDim.x + threadIdx.x;
    int e    = gtid >> 5;
    int lane = gtid & 31;
    if (e >= N_EDGES) return;

    int src = ei[e];
    int dst = ei[N_EDGES + e];
    if ((unsigned)src >= N_NODES || (unsigned)dst >= N_NODES) return;  // diagnostic guard

    float norm = g_dis[src] * g_dis[dst];
    float v = g_h[src * OUT_F + lane] * norm;
    atomicAdd(&g_acc[dst * OUT_F + lane], v);
}

// ---------------------------------------------------------------------------
// K6: out = g_acc + b   (plain coalesced stores only)
__global__ __launch_bounds__(256) void k_finalize(const float* __restrict__ b,
                                                  float* __restrict__ out) {
    int i = blockIdx.x * blockDim.x + threadIdx.x;
    if (i < N_NODES * OUT_F) {
        out[i] = g_acc[i] + b[i & (OUT_F - 1)];
    }
}

// ---------------------------------------------------------------------------
extern "C" void kernel_launch(void* const* d_in, const int* in_sizes, int n_in,
                              void* d_out, int out_size) {
    const float* x  = (const float*)d_in[0];
    const int*   ei = (const int*)d_in[1];     // int32 (harness downcasts int64)
    const float* W  = (const float*)d_in[2];
    const float* b  = (const float*)d_in[3];
    float*       out = (float*)d_out;

    (void)in_sizes; (void)n_in; (void)out_size;

    k_deg_init <<<(N_NODES + 255) / 256, 256>>>();
    k_deg_count<<<(N_EDGES + 255) / 256, 256>>>(ei);
    k_dis      <<<(N_NODES + 255) / 256, 256>>>();
    k_linear   <<<(N_NODES + NODES_PER_BLK - 1) / NODES_PER_BLK, 1024>>>(x, W);
    k_scatter  <<<(N_EDGES * 32 + 255) / 256, 256>>>(ei);
    k_finalize <<<(N_NODES * OUT_F + 255) / 256, 256>>>(b, out);
}

// round 6
// speedup vs baseline: 1.9575x; 1.9575x over previous
#include <cuda_runtime.h>
#include <cstdint>

#define N_NODES 100000
#define N_EDGES 1600000
#define IN_F    128
#define OUT_F   32

// Scratch (__device__ globals; no allocation anywhere in this file).
__device__ int   g_deg[N_NODES];
__device__ float g_dis[N_NODES];
__device__ float g_hs [N_NODES * OUT_F];   // h * dis[node]  (pre-scaled by source norm)
__device__ float g_acc[N_NODES * OUT_F];   // aggregation accumulator

// ---------------------------------------------------------------------------
__global__ void k_deg_init() {
    int i = blockIdx.x * blockDim.x + threadIdx.x;
    if (i < N_NODES) g_deg[i] = 1;                 // self loop
}

__global__ void k_deg_count(const int* __restrict__ ei) {
    int e = blockIdx.x * blockDim.x + threadIdx.x;
    if (e < N_EDGES) atomicAdd(&g_deg[ei[N_EDGES + e]], 1);
}

__global__ void k_dis() {
    int i = blockIdx.x * blockDim.x + threadIdx.x;
    if (i < N_NODES) g_dis[i] = rsqrtf((float)g_deg[i]);
}

// ---------------------------------------------------------------------------
// K4: h = x @ W^T ; g_hs = h*dis ; g_acc = h*dis^2 (self-loop base)
// 256 threads = 8 warps; each warp register-blocks 8 nodes (lane = out feature).
// Per warp: 128 LDS (W, shared once per 8 nodes) + 256 broadcast LDG.128 (x).
#define NODES_PER_WARP 8
#define NODES_PER_BLK  64                           // 8 warps * 8 nodes
__global__ __launch_bounds__(256) void k_linear(const float* __restrict__ x,
                                                const float* __restrict__ W) {
    __shared__ float sWt[IN_F][OUT_F + 1];          // [k][f], padded

    int tid = threadIdx.x;
    #pragma unroll
    for (int i = 0; i < 16; i++) {                  // 4096 W elems / 256 threads
        int idx = tid + i * 256;
        sWt[idx % IN_F][idx / IN_F] = W[idx];
    }
    __syncthreads();

    int warp = tid >> 5;
    int f    = tid & 31;
    int node_base = blockIdx.x * NODES_PER_BLK + warp * NODES_PER_WARP;

    // Clamp node indices for the tail block (store guarded below).
    const float4* xr[NODES_PER_WARP];
    #pragma unroll
    for (int n = 0; n < NODES_PER_WARP; n++) {
        int nc = node_base + n;
        if (nc > N_NODES - 1) nc = N_NODES - 1;
        xr[n] = (const float4*)(x + (size_t)nc * IN_F);
    }

    float acc[NODES_PER_WARP];
    #pragma unroll
    for (int n = 0; n < NODES_PER_WARP; n++) acc[n] = 0.0f;

    #pragma unroll 4
    for (int k4 = 0; k4 < IN_F / 4; k4++) {
        int k = k4 * 4;
        float w0 = sWt[k + 0][f];
        float w1 = sWt[k + 1][f];
        float w2 = sWt[k + 2][f];
        float w3 = sWt[k + 3][f];
        #pragma unroll
        for (int n = 0; n < NODES_PER_WARP; n++) {
            float4 xv = xr[n][k4];                  // warp-broadcast LDG.128
            acc[n] = fmaf(xv.x, w0, acc[n]);
            acc[n] = fmaf(xv.y, w1, acc[n]);
            acc[n] = fmaf(xv.z, w2, acc[n]);
            acc[n] = fmaf(xv.w, w3, acc[n]);
        }
    }

    #pragma unroll
    for (int n = 0; n < NODES_PER_WARP; n++) {
        int node = node_base + n;
        if (node < N_NODES) {
            float d = g_dis[node];
            g_hs [node * OUT_F + f] = acc[n] * d;       // pre-scaled by src norm
            g_acc[node * OUT_F + f] = acc[n] * d * d;   // self-loop term
        }
    }
}

// ---------------------------------------------------------------------------
// K5: edge scatter. 8 lanes per edge (lane covers 4 features via float4).
// v4 = g_hs[src] * dis[dst]; red.global.v4.f32 into g_acc[dst].
__global__ __launch_bounds__(256) void k_scatter(const int* __restrict__ ei) {
    int gtid = blockIdx.x * blockDim.x + threadIdx.x;
    int e  = gtid >> 3;                  // edge (N_EDGES*8 threads, exact)
    int fq = (gtid & 7) * 4;             // feature quad base

    int src = ei[e];                     // broadcast across the 8 lanes
    int dst = ei[N_EDGES + e];

    float nd = g_dis[dst];
    float4 h = *(const float4*)(g_hs + src * OUT_F + fq);   // coalesced 128B/edge
    float4 v = make_float4(h.x * nd, h.y * nd, h.z * nd, h.w * nd);

    float* a = g_acc + dst * OUT_F + fq;
    asm volatile("red.global.add.v4.f32 [%0], {%1, %2, %3, %4};"
                 :: "l"(a), "f"(v.x), "f"(v.y), "f"(v.z), "f"(v.w)
                 : "memory");
}

// ---------------------------------------------------------------------------
// K6: out = g_acc + b   (plain coalesced float4 stores only touch d_out)
__global__ __launch_bounds__(256) void k_finalize(const float* __restrict__ b,
                                                  float* __restrict__ out) {
    int i = blockIdx.x * blockDim.x + threadIdx.x;    // float4 index
    if (i < N_NODES * OUT_F / 4) {
        float4 a = *((const float4*)g_acc + i);
        int fb = (i * 4) & (OUT_F - 1);
        a.x += b[fb + 0]; a.y += b[fb + 1]; a.z += b[fb + 2]; a.w += b[fb + 3];
        *((float4*)out + i) = a;
    }
}

// ---------------------------------------------------------------------------
extern "C" void kernel_launch(void* const* d_in, const int* in_sizes, int n_in,
                              void* d_out, int out_size) {
    const float* x  = (const float*)d_in[0];
    const int*   ei = (const int*)d_in[1];     // int32 (harness downcasts int64)
    const float* W  = (const float*)d_in[2];
    const float* b  = (const float*)d_in[3];
    float*       out = (float*)d_out;

    (void)in_sizes; (void)n_in; (void)out_size;

    k_deg_init <<<(N_NODES + 255) / 256, 256>>>();
    k_deg_count<<<(N_EDGES + 255) / 256, 256>>>(ei);
    k_dis      <<<(N_NODES + 255) / 256, 256>>>();
    k_linear   <<<(N_NODES + NODES_PER_BLK - 1) / NODES_PER_BLK, 256>>>(x, W);
    k_scatter  <<<(N_EDGES * 8) / 256, 256>>>(ei);
    k_finalize <<<(N_NODES * OUT_F / 4 + 255) / 256, 256>>>(b, out);
}